// round 15
// baseline (speedup 1.0000x reference)
#include <cuda_runtime.h>
#include <cuda_fp16.h>
#include <cstdint>

// ---------------- problem constants ----------------
#define E_      8
#define DIN     2048
#define DOUT    2048
#define RANK    8
#define ER      64
#define M_      8192
#define MAIN_OUT (M_*DOUT)
#define W_OUT    (M_*E_)

// ---------------- scratch (device globals) ----------------
__device__ __align__(16) __half g_xh[(size_t)M_ * DIN];
__device__ __align__(16) __half g_Wh[(size_t)DOUT * DIN];
__device__ __align__(16) __half g_hph[(size_t)M_ * ER];
__device__ __align__(16) __half g_Bsh[(size_t)DOUT * ER];
__device__ __align__(16) __half g_Cat[(size_t)80 * DIN];   // rows 0-7 Wr, 8-71 A, 72-79 zero

// ---------------- PTX helpers (baseline sm_80-class only) ----------------
__device__ __forceinline__ uint32_t smem_u32(const void* p) {
    uint32_t a;
    asm("{ .reg .u64 t; cvta.to.shared.u64 t, %1; cvt.u32.u64 %0, t; }" : "=r"(a) : "l"(p));
    return a;
}
#define CP16(saddr, gptr) \
    asm volatile("cp.async.cg.shared.global [%0], [%1], 16;" :: "r"(saddr), "l"(gptr))
#define CP_COMMIT() asm volatile("cp.async.commit_group;" ::: "memory")
#define CP_WAIT(n)  asm volatile("cp.async.wait_group %0;" :: "n"(n) : "memory")

#define LDSM4(r, a) \
    asm volatile("ldmatrix.sync.aligned.m8n8.x4.shared.b16 {%0,%1,%2,%3}, [%4];" \
        : "=r"((r)[0]), "=r"((r)[1]), "=r"((r)[2]), "=r"((r)[3]) : "r"(a))

#define MMA16816(d, a, b) \
    asm volatile("mma.sync.aligned.m16n8k16.row.col.f32.f16.f16.f32 " \
        "{%0,%1,%2,%3}, {%4,%5,%6,%7}, {%8,%9}, {%0,%1,%2,%3};" \
        : "+f"((d)[0]), "+f"((d)[1]), "+f"((d)[2]), "+f"((d)[3]) \
        : "r"((a)[0]), "r"((a)[1]), "r"((a)[2]), "r"((a)[3]), \
          "r"((b)[0]), "r"((b)[1]))

// =====================================================================
// k_cvt: x fp32 -> fp16
// =====================================================================
__global__ void k_cvt(const float* __restrict__ s, __half* __restrict__ h, int n4)
{
    const int i = blockIdx.x * blockDim.x + threadIdx.x;
    if (i >= n4) return;
    const float4 v = ((const float4*)s)[i];
    ((__half2*)h)[2*i]   = __floats2half2_rn(v.x, v.y);
    ((__half2*)h)[2*i+1] = __floats2half2_rn(v.z, v.w);
}

// =====================================================================
// k_prep (fused): Wf->fp16, BsT transpose->fp16, Cat=[Wr;A;0]->fp16
// =====================================================================
#define NW4   (DOUT*DIN/4)
#define NBS   (DOUT*ER)
#define NCAT2 (80*DIN/2)
#define NPREP (NW4+NBS+NCAT2)

__global__ void k_prep(const float* __restrict__ Wf,
                       const float* __restrict__ Wr,
                       const float* __restrict__ A,
                       const float* __restrict__ Bm)
{
    int i = blockIdx.x * blockDim.x + threadIdx.x;
    if (i < NW4) {
        const float4 v = ((const float4*)Wf)[i];
        ((__half2*)g_Wh)[2*i]   = __floats2half2_rn(v.x, v.y);
        ((__half2*)g_Wh)[2*i+1] = __floats2half2_rn(v.z, v.w);
        return;
    }
    i -= NW4;
    if (i < NBS) {
        const int o = i >> 6;
        const int k = i & 63;
        const float v = Bm[(size_t)(k >> 3) * DOUT * RANK + (size_t)o * RANK + (k & 7)];
        g_Bsh[(size_t)o * ER + k] = __float2half_rn(v);
        return;
    }
    i -= NBS;
    if (i < NCAT2) {
        const int row = i >> 10;
        const int c2  = (i & 1023) * 2;
        float v0 = 0.f, v1 = 0.f;
        if (row < 8)       { v0 = Wr[row * DIN + c2];       v1 = Wr[row * DIN + c2 + 1]; }
        else if (row < 72) { v0 = A[(row - 8) * DIN + c2];  v1 = A[(row - 8) * DIN + c2 + 1]; }
        ((__half2*)g_Cat)[i] = __floats2half2_rn(v0, v1);
    }
}

// =====================================================================
// k_hraw_mma: hraw[8192,72] = xh @ Cat^T, fused softmax epilogue
//   (UNCHANGED — measured within helper budget)
// =====================================================================
#define HM_ROWB  144
#define HM_AT    (64*HM_ROWB)
#define HM_BT    (80*HM_ROWB)
#define HM_STAGE (HM_AT+HM_BT)
#define HM_SMEM  (4*HM_STAGE)
#define HM_NCH   32

__device__ __forceinline__ void hm_load(uint32_t s, int c, int tb, int tid)
{
#pragma unroll
    for (int i = 0; i < 4; i++) {
        const int idx = tid + i * 128;
        const int row = idx >> 3, q = idx & 7;
        CP16(s + (uint32_t)(row * HM_ROWB + q * 16),
             g_xh + (size_t)(tb + row) * DIN + c * 64 + q * 8);
    }
#pragma unroll
    for (int i = 0; i < 5; i++) {
        const int idx = tid + i * 128;
        const int row = idx >> 3, q = idx & 7;
        CP16(s + HM_AT + (uint32_t)(row * HM_ROWB + q * 16),
             g_Cat + (size_t)row * DIN + c * 64 + q * 8);
    }
}

__global__ __launch_bounds__(128)
void k_hraw_mma(const float* __restrict__ br, float* __restrict__ wout, int write_w)
{
    extern __shared__ __align__(128) char smh[];
    const uint32_t sb = smem_u32(smh);
    const int tid  = threadIdx.x;
    const int wid  = tid >> 5;
    const int lane = tid & 31;
    const int tb   = blockIdx.x * 64;

    const uint32_t a_off = (uint32_t)((wid * 16 + (lane & 15)) * HM_ROWB + (lane >> 4) * 16);
    const uint32_t b_off = (uint32_t)(((lane & 7) + ((lane >> 4) << 3)) * HM_ROWB
                                      + ((lane >> 3) & 1) * 16);

    float acc[9][4];
#pragma unroll
    for (int nf = 0; nf < 9; nf++)
#pragma unroll
        for (int r = 0; r < 4; r++) acc[nf][r] = 0.f;

    hm_load(sb, 0, tb, tid);
    CP_COMMIT();
    hm_load(sb + HM_STAGE, 1, tb, tid);
    CP_COMMIT();

    for (int c = 0; c < HM_NCH; c++) {
        if (c + 2 < HM_NCH)
            hm_load(sb + (uint32_t)((c + 2) & 3) * HM_STAGE, c + 2, tb, tid);
        CP_COMMIT();
        CP_WAIT(2);
        __syncthreads();

        const uint32_t s_cur = sb + (uint32_t)(c & 3) * HM_STAGE;
#pragma unroll
        for (int ks = 0; ks < 4; ks++) {
            uint32_t ah[4], bh[10][2];
            LDSM4(ah, s_cur + a_off + (uint32_t)(ks * 32));
#pragma unroll
            for (int ng = 0; ng < 5; ng++) {
                uint32_t r[4];
                LDSM4(r, s_cur + HM_AT + b_off + (uint32_t)(ng * 16 * HM_ROWB + ks * 32));
                bh[2*ng][0]   = r[0]; bh[2*ng][1]   = r[1];
                bh[2*ng+1][0] = r[2]; bh[2*ng+1][1] = r[3];
            }
#pragma unroll
            for (int nf = 0; nf < 9; nf++)
                MMA16816(acc[nf], ah, bh[nf]);
        }
    }

    const int q  = lane & 3;
    const int r0 = tb + wid * 16 + (lane >> 2);
    const float b0 = br[2*q], b1 = br[2*q + 1];

    const float a0 = acc[0][0] + b0, a1 = acc[0][1] + b1;
    const float c0 = acc[0][2] + b0, c1 = acc[0][3] + b1;

    float m0 = fmaxf(a0, a1);
    m0 = fmaxf(m0, __shfl_xor_sync(0xffffffffu, m0, 1, 4));
    m0 = fmaxf(m0, __shfl_xor_sync(0xffffffffu, m0, 2, 4));
    float m1 = fmaxf(c0, c1);
    m1 = fmaxf(m1, __shfl_xor_sync(0xffffffffu, m1, 1, 4));
    m1 = fmaxf(m1, __shfl_xor_sync(0xffffffffu, m1, 2, 4));

    const float e00 = __expf(a0 - m0), e01 = __expf(a1 - m0);
    const float e10 = __expf(c0 - m1), e11 = __expf(c1 - m1);
    float s0 = e00 + e01;
    s0 += __shfl_xor_sync(0xffffffffu, s0, 1, 4);
    s0 += __shfl_xor_sync(0xffffffffu, s0, 2, 4);
    float s1 = e10 + e11;
    s1 += __shfl_xor_sync(0xffffffffu, s1, 1, 4);
    s1 += __shfl_xor_sync(0xffffffffu, s1, 2, 4);

    const float p00 = e00 / s0, p01 = e01 / s0;
    const float p10 = e10 / s1, p11 = e11 / s1;

    if (write_w) {
        *(float2*)(wout + (size_t)r0 * E_ + 2*q)       = make_float2(p00, p01);
        *(float2*)(wout + (size_t)(r0 + 8) * E_ + 2*q) = make_float2(p10, p11);
    }

#pragma unroll
    for (int nf = 1; nf < 9; nf++) {
        const int e = nf - 1;
        const int src = (lane & ~3) | (e >> 1);
        const float l0 = __shfl_sync(0xffffffffu, (e & 1) ? p01 : p00, src);
        const float l1 = __shfl_sync(0xffffffffu, (e & 1) ? p11 : p10, src);
        const __half2 h0 = __floats2half2_rn(acc[nf][0] * l0, acc[nf][1] * l0);
        const __half2 h1 = __floats2half2_rn(acc[nf][2] * l1, acc[nf][3] * l1);
        *(__half2*)(g_hph + (size_t)r0 * ER + 8*e + 2*q)       = h0;
        *(__half2*)(g_hph + (size_t)(r0 + 8) * ER + 8*e + 2*q) = h1;
    }
}

// =====================================================================
// Kernel B: mma.sync fp16 GEMM  out = x@Wf^T + bf + hp@BsT^T
//   tile 128x256, 512 threads, 16 warps in 4m x 4n, warp tile 32x64.
//   BK=64, 33 chunks; 3-stage ring, distance 2, sync-before-load.
//   Smem sharing: A read x4, B read x4 -> 25% less LDSM traffic/output.
//   165.9KB smem, 1 CTA/SM (16 warps, same as before).
// =====================================================================
#define NCH      33
#define ROWB     144
#define A_T_B    (128*ROWB)         // 18432
#define B_T_B    (256*ROWB)         // 36864
#define STAGE_B  (A_T_B+B_T_B)      // 55296
#define NSTAGE   3
#define SMEM_GB  (NSTAGE*STAGE_B)   // 165888

__device__ __forceinline__ void stage_load(uint32_t s_stage, int c, int m0, int n0, int tid)
{
    const __half *ga, *gb;
    int stride, koff;
    if (c < 32) {
        ga = g_xh + (size_t)m0 * DIN;
        gb = g_Wh + (size_t)n0 * DIN;
        stride = DIN; koff = c * 64;
    } else {
        ga = g_hph + (size_t)m0 * ER;
        gb = g_Bsh + (size_t)n0 * ER;
        stride = ER; koff = 0;
    }
    // A: 128 rows x 8 x 16B  (1024 slots, 2 iters @512 threads)
#pragma unroll
    for (int i = 0; i < 2; i++) {
        const int idx = tid + i * 512;
        const int row = idx >> 3, q = idx & 7;
        CP16(s_stage + (uint32_t)(row * ROWB + q * 16),
             ga + (size_t)row * stride + koff + q * 8);
    }
    // B: 256 rows x 8 x 16B  (2048 slots, 4 iters)
#pragma unroll
    for (int i = 0; i < 4; i++) {
        const int idx = tid + i * 512;
        const int row = idx >> 3, q = idx & 7;
        CP16(s_stage + A_T_B + (uint32_t)(row * ROWB + q * 16),
             gb + (size_t)row * stride + koff + q * 8);
    }
}

__global__ __launch_bounds__(512, 1)
void k_gemm_mma(const float* __restrict__ bfv, float* __restrict__ out)
{
    extern __shared__ __align__(128) char sm[];
    const uint32_t smem_base = smem_u32(sm);

    const int tid  = threadIdx.x;
    const int wid  = tid >> 5;
    const int lane = tid & 31;
    const int m0 = blockIdx.y * 128;
    const int n0 = blockIdx.x * 256;
    const int warp_m = (wid & 3) * 32;      // 4 m-warps
    const int warp_n = (wid >> 2) * 64;     // 4 n-warps

    const uint32_t a_off = (uint32_t)((warp_m + (lane & 15)) * ROWB + (lane >> 4) * 16);
    const uint32_t b_off = (uint32_t)((warp_n + (lane & 7) + ((lane >> 4) << 3)) * ROWB
                                      + ((lane >> 3) & 1) * 16);

    float acc[2][8][4];
#pragma unroll
    for (int mf = 0; mf < 2; mf++)
#pragma unroll
        for (int nf = 0; nf < 8; nf++)
#pragma unroll
            for (int r = 0; r < 4; r++) acc[mf][nf][r] = 0.f;

    // prologue: chunks 0,1 into slots 0,1
    stage_load(smem_base, 0, m0, n0, tid);
    CP_COMMIT();
    stage_load(smem_base + STAGE_B, 1, m0, n0, tid);
    CP_COMMIT();

    int slot = 0;
    for (int c = 0; c < NCH; c++) {
        CP_WAIT(1);
        __syncthreads();

        if (c + 2 < NCH) {
            const int ns = (slot + 2) % NSTAGE;
            stage_load(smem_base + (uint32_t)ns * STAGE_B, c + 2, m0, n0, tid);
            CP_COMMIT();
        }

        const uint32_t s_cur = smem_base + (uint32_t)slot * STAGE_B;
#pragma unroll
        for (int ks = 0; ks < 4; ks++) {
            uint32_t ah[2][4], bh[8][2];
#pragma unroll
            for (int mf = 0; mf < 2; mf++)
                LDSM4(ah[mf], s_cur + a_off + (uint32_t)(mf * 16 * ROWB + ks * 32));
#pragma unroll
            for (int ng = 0; ng < 4; ng++) {
                uint32_t r[4];
                LDSM4(r, s_cur + A_T_B + b_off + (uint32_t)(ng * 16 * ROWB + ks * 32));
                bh[2*ng][0]   = r[0]; bh[2*ng][1]   = r[1];
                bh[2*ng+1][0] = r[2]; bh[2*ng+1][1] = r[3];
            }
#pragma unroll
            for (int mf = 0; mf < 2; mf++)
#pragma unroll
                for (int nf = 0; nf < 8; nf++)
                    MMA16816(acc[mf][nf], ah[mf], bh[nf]);
        }
        slot = (slot + 1) % NSTAGE;
    }

    // ---- epilogue: acc -> gmem (+bias)
    float2 bias[8];
#pragma unroll
    for (int nf = 0; nf < 8; nf++) {
        const int n = n0 + warp_n + nf * 8 + 2 * (lane & 3);
        bias[nf] = *(const float2*)(bfv + n);
    }
    const int mrow = m0 + warp_m + (lane >> 2);
    const int ncol = n0 + warp_n + 2 * (lane & 3);
#pragma unroll
    for (int mf = 0; mf < 2; mf++) {
#pragma unroll
        for (int nf = 0; nf < 8; nf++) {
            float* p0 = out + (size_t)(mrow + mf * 16) * DOUT + ncol + nf * 8;
            float* p1 = p0 + 8 * DOUT;
            float2 v0 = {acc[mf][nf][0] + bias[nf].x, acc[mf][nf][1] + bias[nf].y};
            float2 v1 = {acc[mf][nf][2] + bias[nf].x, acc[mf][nf][3] + bias[nf].y};
            *(float2*)p0 = v0;
            *(float2*)p1 = v1;
        }
    }
}

// =====================================================================
// launch
// =====================================================================
extern "C" void kernel_launch(void* const* d_in, const int* in_sizes, int n_in,
                              void* d_out, int out_size)
{
    const float* x  = (const float*)d_in[0];
    const float* Wf = (const float*)d_in[1];
    const float* bf = (const float*)d_in[2];
    const float* Wr = (const float*)d_in[3];
    const float* br = (const float*)d_in[4];
    const float* A  = (const float*)d_in[5];
    const float* Bm = (const float*)d_in[6];
    float* out = (float*)d_out;

    const int write_w = (out_size >= MAIN_OUT + W_OUT) ? 1 : 0;

    __half* xh;
    cudaGetSymbolAddress((void**)&xh, g_xh);

    cudaFuncSetAttribute(k_hraw_mma, cudaFuncAttributeMaxDynamicSharedMemorySize, HM_SMEM);
    cudaFuncSetAttribute(k_gemm_mma, cudaFuncAttributeMaxDynamicSharedMemorySize, SMEM_GB);

    k_cvt<<<(M_ * DIN / 4 + 255) / 256, 256>>>(x, xh, M_ * DIN / 4);
    k_prep<<<(NPREP + 255) / 256, 256>>>(Wf, Wr, A, Bm);
    k_hraw_mma<<<M_ / 64, 128, HM_SMEM>>>(br, out + MAIN_OUT, write_w);
    k_gemm_mma<<<dim3(DOUT / 256, M_ / 128), 512, SMEM_GB>>>(bf, out);
}

// round 16
// speedup vs baseline: 1.0857x; 1.0857x over previous
#include <cuda_runtime.h>
#include <cuda_fp16.h>
#include <cstdint>

// ---------------- problem constants ----------------
#define E_      8
#define DIN     2048
#define DOUT    2048
#define RANK    8
#define ER      64
#define M_      8192
#define MAIN_OUT (M_*DOUT)
#define W_OUT    (M_*E_)

// ---------------- scratch (device globals) ----------------
__device__ __align__(16) __half g_xh[(size_t)M_ * DIN];
__device__ __align__(16) __half g_Wh[(size_t)DOUT * DIN];
__device__ __align__(16) __half g_hph[(size_t)M_ * ER];
__device__ __align__(16) __half g_Bsh[(size_t)DOUT * ER];
__device__ __align__(16) __half g_Cat[(size_t)80 * DIN];   // rows 0-7 Wr, 8-71 A, 72-79 zero

// ---------------- PTX helpers (baseline sm_80-class only) ----------------
__device__ __forceinline__ uint32_t smem_u32(const void* p) {
    uint32_t a;
    asm("{ .reg .u64 t; cvta.to.shared.u64 t, %1; cvt.u32.u64 %0, t; }" : "=r"(a) : "l"(p));
    return a;
}
#define CP16(saddr, gptr) \
    asm volatile("cp.async.cg.shared.global [%0], [%1], 16;" :: "r"(saddr), "l"(gptr))
#define CP_COMMIT() asm volatile("cp.async.commit_group;" ::: "memory")
#define CP_WAIT(n)  asm volatile("cp.async.wait_group %0;" :: "n"(n) : "memory")

#define LDSM4(r, a) \
    asm volatile("ldmatrix.sync.aligned.m8n8.x4.shared.b16 {%0,%1,%2,%3}, [%4];" \
        : "=r"((r)[0]), "=r"((r)[1]), "=r"((r)[2]), "=r"((r)[3]) : "r"(a))

#define MMA16816(d, a, b) \
    asm volatile("mma.sync.aligned.m16n8k16.row.col.f32.f16.f16.f32 " \
        "{%0,%1,%2,%3}, {%4,%5,%6,%7}, {%8,%9}, {%0,%1,%2,%3};" \
        : "+f"((d)[0]), "+f"((d)[1]), "+f"((d)[2]), "+f"((d)[3]) \
        : "r"((a)[0]), "r"((a)[1]), "r"((a)[2]), "r"((a)[3]), \
          "r"((b)[0]), "r"((b)[1]))

// =====================================================================
// k_prep (fused): Wf->fp16, BsT transpose->fp16, Cat=[Wr;A;0]->fp16
// =====================================================================
#define NW4   (DOUT*DIN/4)
#define NBS   (DOUT*ER)
#define NCAT2 (80*DIN/2)
#define NPREP (NW4+NBS+NCAT2)

__global__ void k_prep(const float* __restrict__ Wf,
                       const float* __restrict__ Wr,
                       const float* __restrict__ A,
                       const float* __restrict__ Bm)
{
    int i = blockIdx.x * blockDim.x + threadIdx.x;
    if (i < NW4) {
        const float4 v = ((const float4*)Wf)[i];
        ((__half2*)g_Wh)[2*i]   = __floats2half2_rn(v.x, v.y);
        ((__half2*)g_Wh)[2*i+1] = __floats2half2_rn(v.z, v.w);
        return;
    }
    i -= NW4;
    if (i < NBS) {
        const int o = i >> 6;
        const int k = i & 63;
        const float v = Bm[(size_t)(k >> 3) * DOUT * RANK + (size_t)o * RANK + (k & 7)];
        g_Bsh[(size_t)o * ER + k] = __float2half_rn(v);
        return;
    }
    i -= NBS;
    if (i < NCAT2) {
        const int row = i >> 10;
        const int c2  = (i & 1023) * 2;
        float v0 = 0.f, v1 = 0.f;
        if (row < 8)       { v0 = Wr[row * DIN + c2];       v1 = Wr[row * DIN + c2 + 1]; }
        else if (row < 72) { v0 = A[(row - 8) * DIN + c2];  v1 = A[(row - 8) * DIN + c2 + 1]; }
        ((__half2*)g_Cat)[i] = __floats2half2_rn(v0, v1);
    }
}

// =====================================================================
// k_hraw_mma (fused cvt): per 64-token block
//   - reads x fp32 (register-prefetched), converts -> fp16 A-tile in smem
//     AND writes g_xh for the main GEMM
//   - hraw = xh @ Cat^T via mma.sync; fused softmax epilogue
//   A: single fixed smem buffer (written+read inside one barrier interval).
//   B (Cat): 4-stage cp.async ring, prefetch distance 2 (proven pattern).
// =====================================================================
#define HM_ROWB  144
#define HM_AT    (64*HM_ROWB)        // 9216 (A tile, fixed)
#define HM_BT    (80*HM_ROWB)        // 11520 (B stage)
#define HM_SMEM  (HM_AT + 4*HM_BT)   // 55296
#define HM_NCH   32

__device__ __forceinline__ void hm_loadB(uint32_t sB, int c, int tid)
{
#pragma unroll
    for (int i = 0; i < 5; i++) {
        const int idx = tid + i * 128;
        const int row = idx >> 3, q = idx & 7;
        CP16(sB + (uint32_t)(row * HM_ROWB + q * 16),
             g_Cat + (size_t)row * DIN + c * 64 + q * 8);
    }
}

__global__ __launch_bounds__(128)
void k_hraw_mma(const float* __restrict__ x,
                const float* __restrict__ br,
                float* __restrict__ wout, int write_w)
{
    extern __shared__ __align__(128) char smh[];
    const uint32_t sb   = smem_u32(smh);            // A tile (fixed)
    const uint32_t sbB  = sb + HM_AT;               // B ring base
    const int tid  = threadIdx.x;
    const int wid  = tid >> 5;
    const int lane = tid & 31;
    const int tb   = blockIdx.x * 64;

    // x-conversion mapping: thread t -> row = t>>1, col half = (t&1)*32
    const int xrow = tid >> 1;
    const int xcb  = (tid & 1) * 32;
    const float* xsrc = x + (size_t)(tb + xrow) * DIN + xcb;
    __half* xdst = g_xh + (size_t)(tb + xrow) * DIN + xcb;
    const uint32_t sA = sb + (uint32_t)(xrow * HM_ROWB + xcb * 2);

    const uint32_t a_off = (uint32_t)((wid * 16 + (lane & 15)) * HM_ROWB + (lane >> 4) * 16);
    const uint32_t b_off = (uint32_t)(((lane & 7) + ((lane >> 4) << 3)) * HM_ROWB
                                      + ((lane >> 3) & 1) * 16);

    float acc[9][4];
#pragma unroll
    for (int nf = 0; nf < 9; nf++)
#pragma unroll
        for (int r = 0; r < 4; r++) acc[nf][r] = 0.f;

    // B prologue: chunks 0,1
    hm_loadB(sbB, 0, tid);
    CP_COMMIT();
    hm_loadB(sbB + HM_BT, 1, tid);
    CP_COMMIT();

    // x prologue: chunk 0 into regs
    float4 xr[8];
#pragma unroll
    for (int j = 0; j < 8; j++) xr[j] = *(const float4*)(xsrc + j * 4);

    for (int c = 0; c < HM_NCH; c++) {
        if (c + 2 < HM_NCH)
            hm_loadB(sbB + (uint32_t)((c + 2) & 3) * HM_BT, c + 2, tid);
        CP_COMMIT();
        CP_WAIT(2);

        // convert chunk c: regs -> fp16 smem A tile + g_xh
#pragma unroll
        for (int j = 0; j < 8; j++) {
            const __half2 h0 = __floats2half2_rn(xr[j].x, xr[j].y);
            const __half2 h1 = __floats2half2_rn(xr[j].z, xr[j].w);
            uint2 pk;
            pk.x = *(const uint32_t*)&h0;
            pk.y = *(const uint32_t*)&h1;
            *(uint2*)(smh + (sA - sb) + j * 8) = pk;
            *(uint2*)(xdst + c * 64 + j * 4)   = pk;
        }
        // prefetch chunk c+1 fp32 into regs (hidden under compute)
        if (c + 1 < HM_NCH) {
#pragma unroll
            for (int j = 0; j < 8; j++)
                xr[j] = *(const float4*)(xsrc + (c + 1) * 64 + j * 4);
        }
        __syncthreads();   // A STS visible + B(c) arrival ordered for all warps

        const uint32_t s_curB = sbB + (uint32_t)(c & 3) * HM_BT;
#pragma unroll
        for (int ks = 0; ks < 4; ks++) {
            uint32_t ah[4], bh[10][2];
            LDSM4(ah, sb + a_off + (uint32_t)(ks * 32));
#pragma unroll
            for (int ng = 0; ng < 5; ng++) {
                uint32_t r[4];
                LDSM4(r, s_curB + b_off + (uint32_t)(ng * 16 * HM_ROWB + ks * 32));
                bh[2*ng][0]   = r[0]; bh[2*ng][1]   = r[1];
                bh[2*ng+1][0] = r[2]; bh[2*ng+1][1] = r[3];
            }
#pragma unroll
            for (int nf = 0; nf < 9; nf++)
                MMA16816(acc[nf], ah, bh[nf]);
        }
        __syncthreads();   // all warps done with A tile before next chunk's STS
    }

    // ---- fused epilogue: softmax over cols 0..7, fold into cols 8..71
    const int q  = lane & 3;
    const int r0 = tb + wid * 16 + (lane >> 2);
    const float b0 = br[2*q], b1 = br[2*q + 1];

    const float a0 = acc[0][0] + b0, a1 = acc[0][1] + b1;
    const float c0 = acc[0][2] + b0, c1 = acc[0][3] + b1;

    float m0 = fmaxf(a0, a1);
    m0 = fmaxf(m0, __shfl_xor_sync(0xffffffffu, m0, 1, 4));
    m0 = fmaxf(m0, __shfl_xor_sync(0xffffffffu, m0, 2, 4));
    float m1 = fmaxf(c0, c1);
    m1 = fmaxf(m1, __shfl_xor_sync(0xffffffffu, m1, 1, 4));
    m1 = fmaxf(m1, __shfl_xor_sync(0xffffffffu, m1, 2, 4));

    const float e00 = __expf(a0 - m0), e01 = __expf(a1 - m0);
    const float e10 = __expf(c0 - m1), e11 = __expf(c1 - m1);
    float s0 = e00 + e01;
    s0 += __shfl_xor_sync(0xffffffffu, s0, 1, 4);
    s0 += __shfl_xor_sync(0xffffffffu, s0, 2, 4);
    float s1 = e10 + e11;
    s1 += __shfl_xor_sync(0xffffffffu, s1, 1, 4);
    s1 += __shfl_xor_sync(0xffffffffu, s1, 2, 4);

    const float p00 = e00 / s0, p01 = e01 / s0;
    const float p10 = e10 / s1, p11 = e11 / s1;

    if (write_w) {
        *(float2*)(wout + (size_t)r0 * E_ + 2*q)       = make_float2(p00, p01);
        *(float2*)(wout + (size_t)(r0 + 8) * E_ + 2*q) = make_float2(p10, p11);
    }

#pragma unroll
    for (int nf = 1; nf < 9; nf++) {
        const int e = nf - 1;
        const int src = (lane & ~3) | (e >> 1);
        const float l0 = __shfl_sync(0xffffffffu, (e & 1) ? p01 : p00, src);
        const float l1 = __shfl_sync(0xffffffffu, (e & 1) ? p11 : p10, src);
        const __half2 h0 = __floats2half2_rn(acc[nf][0] * l0, acc[nf][1] * l0);
        const __half2 h1 = __floats2half2_rn(acc[nf][2] * l1, acc[nf][3] * l1);
        *(__half2*)(g_hph + (size_t)r0 * ER + 8*e + 2*q)       = h0;
        *(__half2*)(g_hph + (size_t)(r0 + 8) * ER + 8*e + 2*q) = h1;
    }
}

// =====================================================================
// Kernel B: mma.sync fp16 GEMM  out = x@Wf^T + bf + hp@BsT^T
//   EXACT round-13 config (measured 203.0us): tile 128x128, BK=64,
//   33 chunks, 3-stage ring distance 2 sync-before-load,
//   8 warps (2m x 4n), warp tile 64x32, 110.6KB smem -> 2 CTAs/SM.
// =====================================================================
#define NCH      33
#define ROWB     144
#define TILE_B   (128*ROWB)
#define STAGE_B  (2*TILE_B)
#define NSTAGE   3
#define SMEM_GB  (NSTAGE*STAGE_B)   // 110592

__device__ __forceinline__ void stage_load(uint32_t s_stage, int c, int m0, int n0, int tid)
{
    const __half *ga, *gb;
    int stride, koff;
    if (c < 32) {
        ga = g_xh + (size_t)m0 * DIN;
        gb = g_Wh + (size_t)n0 * DIN;
        stride = DIN; koff = c * 64;
    } else {
        ga = g_hph + (size_t)m0 * ER;
        gb = g_Bsh + (size_t)n0 * ER;
        stride = ER; koff = 0;
    }
#pragma unroll
    for (int i = 0; i < 4; i++) {
        const int idx = tid + i * 256;
        const int row = idx >> 3;
        const int q   = idx & 7;
        const uint32_t so = (uint32_t)(row * ROWB + q * 16);
        const size_t go = (size_t)row * stride + koff + q * 8;
        CP16(s_stage + so,          ga + go);
        CP16(s_stage + TILE_B + so, gb + go);
    }
}

__global__ __launch_bounds__(256, 2)
void k_gemm_mma(const float* __restrict__ bfv, float* __restrict__ out)
{
    extern __shared__ __align__(128) char sm[];
    const uint32_t smem_base = smem_u32(sm);

    const int tid  = threadIdx.x;
    const int wid  = tid >> 5;
    const int lane = tid & 31;
    const int m0 = blockIdx.y * 128;
    const int n0 = blockIdx.x * 128;
    const int warp_m = (wid & 1) * 64;
    const int warp_n = (wid >> 1) * 32;

    const uint32_t a_off = (uint32_t)((warp_m + (lane & 15)) * ROWB + (lane >> 4) * 16);
    const uint32_t b_off = (uint32_t)((warp_n + (lane & 7) + ((lane >> 4) << 3)) * ROWB
                                      + ((lane >> 3) & 1) * 16);

    float acc[4][4][4];
#pragma unroll
    for (int mf = 0; mf < 4; mf++)
#pragma unroll
        for (int nf = 0; nf < 4; nf++)
#pragma unroll
            for (int r = 0; r < 4; r++) acc[mf][nf][r] = 0.f;

    stage_load(smem_base, 0, m0, n0, tid);
    CP_COMMIT();
    stage_load(smem_base + STAGE_B, 1, m0, n0, tid);
    CP_COMMIT();

    int slot = 0;
    for (int c = 0; c < NCH; c++) {
        CP_WAIT(1);
        __syncthreads();

        if (c + 2 < NCH) {
            const int ns = (slot + 2) % NSTAGE;
            stage_load(smem_base + (uint32_t)ns * STAGE_B, c + 2, m0, n0, tid);
            CP_COMMIT();
        }

        const uint32_t s_cur = smem_base + (uint32_t)slot * STAGE_B;
#pragma unroll
        for (int ks = 0; ks < 4; ks++) {
            uint32_t ah[4][4], bh[4][2];
#pragma unroll
            for (int mf = 0; mf < 4; mf++)
                LDSM4(ah[mf], s_cur + a_off + (uint32_t)(mf * 16 * ROWB + ks * 32));
#pragma unroll
            for (int ng = 0; ng < 2; ng++) {
                uint32_t r[4];
                LDSM4(r, s_cur + TILE_B + b_off + (uint32_t)(ng * 16 * ROWB + ks * 32));
                bh[2*ng][0]   = r[0]; bh[2*ng][1]   = r[1];
                bh[2*ng+1][0] = r[2]; bh[2*ng+1][1] = r[3];
            }
#pragma unroll
            for (int mf = 0; mf < 4; mf++)
#pragma unroll
                for (int nf = 0; nf < 4; nf++)
                    MMA16816(acc[mf][nf], ah[mf], bh[nf]);
        }
        slot = (slot + 1) % NSTAGE;
    }

    float2 bias[4];
#pragma unroll
    for (int nf = 0; nf < 4; nf++) {
        const int n = n0 + warp_n + nf * 8 + 2 * (lane & 3);
        bias[nf] = *(const float2*)(bfv + n);
    }
    const int mrow = m0 + warp_m + (lane >> 2);
    const int ncol = n0 + warp_n + 2 * (lane & 3);
#pragma unroll
    for (int mf = 0; mf < 4; mf++) {
#pragma unroll
        for (int nf = 0; nf < 4; nf++) {
            float* p0 = out + (size_t)(mrow + mf * 16) * DOUT + ncol + nf * 8;
            float* p1 = p0 + 8 * DOUT;
            float2 v0 = {acc[mf][nf][0] + bias[nf].x, acc[mf][nf][1] + bias[nf].y};
            float2 v1 = {acc[mf][nf][2] + bias[nf].x, acc[mf][nf][3] + bias[nf].y};
            *(float2*)p0 = v0;
            *(float2*)p1 = v1;
        }
    }
}

// =====================================================================
// launch
// =====================================================================
extern "C" void kernel_launch(void* const* d_in, const int* in_sizes, int n_in,
                              void* d_out, int out_size)
{
    const float* x  = (const float*)d_in[0];
    const float* Wf = (const float*)d_in[1];
    const float* bf = (const float*)d_in[2];
    const float* Wr = (const float*)d_in[3];
    const float* br = (const float*)d_in[4];
    const float* A  = (const float*)d_in[5];
    const float* Bm = (const float*)d_in[6];
    float* out = (float*)d_out;

    const int write_w = (out_size >= MAIN_OUT + W_OUT) ? 1 : 0;

    cudaFuncSetAttribute(k_hraw_mma, cudaFuncAttributeMaxDynamicSharedMemorySize, HM_SMEM);
    cudaFuncSetAttribute(k_gemm_mma, cudaFuncAttributeMaxDynamicSharedMemorySize, SMEM_GB);

    k_prep<<<(NPREP + 255) / 256, 256>>>(Wf, Wr, A, Bm);
    k_hraw_mma<<<M_ / 64, 128, HM_SMEM>>>(x, br, out + MAIN_OUT, write_w);
    k_gemm_mma<<<dim3(DOUT / 128, M_ / 128), 256, SMEM_GB>>>(bf, out);
}